// round 14
// baseline (speedup 1.0000x reference)
#include <cuda_runtime.h>
#include <cuda_bf16.h>
#include <cstdint>
#include <cstddef>

// Problem constants
#define BB     32
#define TT     2048
#define FIN    63
#define FDIM   64
#define LUDIM  640
#define NCH    32      // chunks of 64 timesteps
#define TCH    64
#define NCHAIN 2048

// smem layout — total 113,664 B -> 2 CTAs/SM
// X region (0..18432) is DEAD after A-fragment preload; stages ping-pong
// between it and the K region (18432..36864). Both are 2 x 9216 B.
#define XSTR   72      // dX row stride (bf16 elems)
#define KSTR   72      // K stage stride (bf16 elems): 64 cols + 8 pad
#define PSTR   260     // sP row stride (floats)
#define OFF_XH 0
#define OFF_XL 9216
#define OFF_KA 18432           // stage buffer A (even stages)
#define KB_HALF 9216           // hi/lo halves within a stage buffer
#define OFF_MAPS 36864         // 4 subchunks * 64 u * 10 coeffs * 4B = 10240
#define OFF_SP 47104
#define SMEM_TOTAL (OFF_SP + TCH * PSTR * 4)   // 113664

#define WSTRIDE 20     // g_W record stride (floats), 80 B = 16B-aligned

// Precomputed bf16 hi/lo split of kernel, [f][lu]
__device__ __nv_bfloat16 g_KH[FDIM * LUDIM];
__device__ __nv_bfloat16 g_KL[FDIM * LUDIM];
// g_W layout: [chain][c][20]
__device__ float g_W[(size_t)NCHAIN * NCH * WSTRIDE];

// ---------------- PTX helpers ----------------
__device__ __forceinline__ uint32_t smem_u32(const void* p) {
    uint32_t a;
    asm("{ .reg .u64 t; cvta.to.shared.u64 t, %1; cvt.u32.u64 %0, t; }" : "=r"(a) : "l"(p));
    return a;
}
__device__ __forceinline__ void ldsm_x4(uint32_t& r0, uint32_t& r1, uint32_t& r2, uint32_t& r3,
                                        uint32_t addr) {
    asm volatile("ldmatrix.sync.aligned.m8n8.x4.shared.b16 {%0,%1,%2,%3}, [%4];"
                 : "=r"(r0), "=r"(r1), "=r"(r2), "=r"(r3) : "r"(addr));
}
__device__ __forceinline__ void ldsm_x4t(uint32_t& r0, uint32_t& r1, uint32_t& r2, uint32_t& r3,
                                         uint32_t addr) {
    asm volatile("ldmatrix.sync.aligned.m8n8.x4.trans.shared.b16 {%0,%1,%2,%3}, [%4];"
                 : "=r"(r0), "=r"(r1), "=r"(r2), "=r"(r3) : "r"(addr));
}
__device__ __forceinline__ void mma_bf16(float* c, const uint32_t* a, uint32_t b0, uint32_t b1) {
    asm volatile(
        "mma.sync.aligned.m16n8k16.row.col.f32.bf16.bf16.f32 "
        "{%0,%1,%2,%3}, {%4,%5,%6,%7}, {%8,%9}, {%0,%1,%2,%3};"
        : "+f"(c[0]), "+f"(c[1]), "+f"(c[2]), "+f"(c[3])
        : "r"(a[0]), "r"(a[1]), "r"(a[2]), "r"(a[3]), "r"(b0), "r"(b1));
}

// ---------------- Chen map (combine kernel) ----------------
struct SigMap {
    float Y0,S2,S5,S9,W54,W98,W987,E1,E3,E4,E43,E6,E7,E76,E8,E87,E876;
};

__device__ __forceinline__ SigMap sig_compose(const SigMap& A, const SigMap& B) {
    SigMap C;
    C.E1   = A.E1 + B.E1;
    C.E3   = A.E3 + B.E3;
    C.E6   = A.E6 + B.E6;
    C.E4   = A.E4 + B.E4;
    C.E43  = A.E43 + A.E3 * B.E4 + B.E43;
    C.E7   = A.E7 + B.E7;
    C.E76  = A.E76 + A.E6 * B.E7 + B.E76;
    C.E8   = A.E8 + B.E8;
    C.E87  = A.E87 + A.E7 * B.E8 + B.E87;
    C.E876 = A.E876 + A.E76 * B.E8 + A.E6 * B.E87 + B.E876;
    C.S2   = A.S2 + B.S2;
    C.S5   = A.S5 + B.S5;
    C.S9   = A.S9 + B.S9;
    C.W54  = A.W54 + A.E4 * B.S5 + B.W54;
    C.W98  = A.W98 + A.E8 * B.S9 + B.W98;
    C.W987 = A.W987 + A.E87 * B.S9 + A.E7 * B.W98 + B.W987;
    C.Y0   = A.Y0 + B.Y0 + A.E1 * B.S2 + A.E43 * B.S5 + A.E3 * B.W54
           + A.E876 * B.S9 + A.E76 * B.W98 + A.E6 * B.W987;
    return C;
}

// ---------------- Prep: K -> bf16 hi/lo in gmem ----------------
extern "C" __global__ void __launch_bounds__(256)
lrsig_prep(const float* __restrict__ kern)
{
    int i = blockIdx.x * 256 + threadIdx.x;
    if (i < FDIM * LUDIM) {
        float v = kern[i];
        __nv_bfloat16 hi = __float2bfloat16(v);
        g_KH[i] = hi;
        g_KL[i] = __float2bfloat16(v - __bfloat162float(hi));
    }
}

// ---------------- Fused kernel: m = dX @ K + 3-pass chunk scan ----------------
// Grid (NCH, BB) = (32, 32), 256 threads, 2 CTAs/SM.
// 10 stages of 64 lu cols; ping-pong K buffers; ONE sync per stage.
// Passes: A = levels 0-2, B = levels 3-5, C = levels 6-9; sP reused per pass.
extern "C" __global__ void __launch_bounds__(256, 2)
lrsig_fused(const float* __restrict__ x, const float* __restrict__ kern)
{
    extern __shared__ char smem[];
    float* sP    = reinterpret_cast<float*>(smem + OFF_SP);
    float* sMaps = reinterpret_cast<float*>(smem + OFF_MAPS);
    const uint32_t sb = smem_u32(smem);

    const int tid  = threadIdx.x;
    const int lane = tid & 31;
    const int w    = tid >> 5;
    const int wt   = w & 3;
    const int wn   = w >> 2;
    const int c    = blockIdx.x;
    const int b    = blockIdx.y;
    const int t0   = c * TCH;

    // K prefetch: per stage buffer = 64 rows x 8 uint4 per half = 512 uint4,
    // 2 per thread per half. Dest rows are 9 uint4 (KSTR=72, pad never read).
    const uint4* srcH = reinterpret_cast<const uint4*>(g_KH);  // 80 uint4/row
    const uint4* srcL = reinterpret_cast<const uint4*>(g_KL);
    const int f0 = tid >> 3, v0 = tid & 7;
    const int f1 = f0 + 32;

    // Prefetch stage 0 (overlaps dX fill)
    uint4 rH0 = srcH[f0 * 80 + v0], rH1 = srcH[f1 * 80 + v0];
    uint4 rL0 = srcL[f0 * 80 + v0], rL1 = srcL[f1 * 80 + v0];

    // ---- dX tile (hi/lo bf16 split), [t][f], stride 72; exact fp32 diff ----
    for (int e = tid; e < TCH * FDIM; e += 256) {
        int tl = e >> 6, f = e & 63;
        int t = t0 + tl;
        float v;
        if (t == 0)      v = 0.0f;                                   // m[0] = 0
        else if (f < FIN) {
            const float* xr = x + ((size_t)b * TT + t) * FIN + f;
            v = xr[0] - xr[-FIN];
        } else            v = 2.0f / 2047.0f;                        // d(time)
        __nv_bfloat16 hi = __float2bfloat16(v);
        __nv_bfloat16 lo = __float2bfloat16(v - __bfloat162float(hi));
        int off = (tl * XSTR + f) * 2;
        *reinterpret_cast<__nv_bfloat16*>(smem + OFF_XH + off) = hi;
        *reinterpret_cast<__nv_bfloat16*>(smem + OFF_XL + off) = lo;
    }
    __syncthreads();

    // ---- Preload A fragments once (X smem region is DEAD afterwards) ----
    const uint32_t a_off = (uint32_t)((lane & 15) * XSTR + ((lane >> 4) << 3)) * 2;
    uint32_t Ah[4][4], Al[4][4];
#pragma unroll
    for (int ks = 0; ks < 4; ks++) {
        uint32_t ra = (uint32_t)(wt * 16 * XSTR + ks * 16) * 2 + a_off;
        ldsm_x4(Ah[ks][0], Ah[ks][1], Ah[ks][2], Ah[ks][3], sb + OFF_XH + ra);
        ldsm_x4(Al[ks][0], Al[ks][1], Al[ks][2], Al[ks][3], sb + OFF_XL + ra);
    }

    const uint32_t b_off = (uint32_t)((((lane >> 3) & 1) * 8 + (lane & 7)) * KSTR
                                      + ((lane >> 4) << 3)) * 2;

    float Y0acc = 0.0f;

    // ---- Stage loop: 10 stages; ping-pong buffers; 1 sync/stage ----
    for (int j = 0; j < 10; j++) {
        const uint32_t kb = (j & 1) ? 0u : (uint32_t)OFF_KA;  // odd -> dead X region
        // Commit prefetched K stage (targets buffer last read at stage j-2;
        // safe: its readers finished before sync(j-1), this STS is after it)
        {
            uint4* dH = reinterpret_cast<uint4*>(smem + kb);
            uint4* dL = reinterpret_cast<uint4*>(smem + kb + KB_HALF);
            dH[f0 * 9 + v0] = rH0;  dH[f1 * 9 + v0] = rH1;
            dL[f0 * 9 + v0] = rL0;  dL[f1 * 9 + v0] = rL1;
        }
        __syncthreads();
        if (j < 9) {
            rH0 = srcH[f0 * 80 + (j + 1) * 8 + v0];
            rH1 = srcH[f1 * 80 + (j + 1) * 8 + v0];
            rL0 = srcL[f0 * 80 + (j + 1) * 8 + v0];
            rL1 = srcL[f1 * 80 + (j + 1) * 8 + v0];
        }

        float C[4][4];
#pragma unroll
        for (int nt = 0; nt < 4; nt++)
#pragma unroll
            for (int i = 0; i < 4; i++) C[nt][i] = 0.0f;

#pragma unroll
        for (int ks = 0; ks < 4; ks++)
#pragma unroll
            for (int q = 0; q < 2; q++) {
                uint32_t rb = (uint32_t)(ks * 16 * KSTR + (wn * 32 + q * 16)) * 2 + b_off;
                uint32_t Bh[4], Bl[4];
                ldsm_x4t(Bh[0], Bh[1], Bh[2], Bh[3], sb + kb + rb);
                ldsm_x4t(Bl[0], Bl[1], Bl[2], Bl[3], sb + kb + KB_HALF + rb);
#pragma unroll
                for (int p = 0; p < 2; p++) {
                    float* cc = C[q * 2 + p];
                    mma_bf16(cc, Ah[ks], Bh[p * 2], Bh[p * 2 + 1]);
                    mma_bf16(cc, Al[ks], Bh[p * 2], Bh[p * 2 + 1]);
                    mma_bf16(cc, Ah[ks], Bl[p * 2], Bl[p * 2 + 1]);
                }
            }

        // Epilogue into sP at pass-local columns
        {
            const int ps = (j < 3) ? 0 : ((j < 6) ? 3 : 6);
            const int cb = (j - ps) * 64;
            int r = wt * 16 + (lane >> 2);
#pragma unroll
            for (int nt = 0; nt < 4; nt++) {
                int col = cb + wn * 32 + nt * 8 + (lane & 3) * 2;
                float* q0 = sP + (size_t)r * PSTR + col;
                float* q1 = sP + (size_t)(r + 8) * PSTR + col;
                *reinterpret_cast<float2*>(q0) = make_float2(C[nt][0], C[nt][1]);
                *reinterpret_cast<float2*>(q1) = make_float2(C[nt][2], C[nt][3]);
            }
        }

        // ---- Pass-end scans ----
        if (j == 2 || j == 5 || j == 9) {
            __syncthreads();     // sP complete for this pass
            const int u  = tid & 63;
            const int qc = tid >> 6;        // 0..3, 16 rows each
            const int r0 = qc * 16;
            float* mp = sMaps + (size_t)(qc * 64 + u) * 10;

            if (j == 2) {
                float y0 = 0.f, e1 = 0.f, S2 = 0.f, W21 = 0.f;
#pragma unroll 4
                for (int i = 0; i < 16; i++) {
                    const float* p = sP + (size_t)(r0 + i) * PSTR + u;
                    float m0 = p[0], m1 = p[64], m2 = p[128];
                    y0 += m0;
                    W21 = fmaf(m2, e1, W21);  S2 += m2;  e1 += m1;
                }
                mp[0] = y0; mp[1] = e1; mp[2] = S2; mp[3] = W21;
                __syncthreads();
                if (tid < 64) {
                    float Y = 0.f, E1 = 0.f, S2t = 0.f, W21t = 0.f;
#pragma unroll
                    for (int q = 0; q < 4; q++) {
                        const float* s = sMaps + (size_t)(q * 64 + tid) * 10;
                        W21t += E1 * s[2] + s[3];
                        E1   += s[1];  S2t += s[2];  Y += s[0];
                    }
                    Y0acc = Y + W21t;
                    float* wp = g_W + ((size_t)(b * 64 + tid) * NCH + c) * WSTRIDE;
                    wp[7] = E1;  wp[1] = S2t;
                }
            } else if (j == 5) {
                float e3=0.f,e4=0.f,e43=0.f,S5=0.f,W54=0.f,W543=0.f;
#pragma unroll 4
                for (int i = 0; i < 16; i++) {
                    const float* p = sP + (size_t)(r0 + i) * PSTR + u;
                    float m3 = p[0], m4 = p[64], m5 = p[128];
                    W54  = fmaf(m5, e4,  W54);
                    W543 = fmaf(m5, e43, W543);  S5 += m5;
                    e43  = fmaf(m4, e3,  e43);
                    e3 += m3;  e4 += m4;
                }
                mp[0]=e3; mp[1]=e4; mp[2]=e43; mp[3]=S5; mp[4]=W54; mp[5]=W543;
                __syncthreads();
                if (tid < 64) {
                    float E3=0.f,E4=0.f,E43=0.f,S5t=0.f,W54t=0.f,W543t=0.f;
#pragma unroll
                    for (int q = 0; q < 4; q++) {
                        const float* s = sMaps + (size_t)(q * 64 + tid) * 10;
                        W543t += E43 * s[3] + E3 * s[4] + s[5];
                        W54t  += E4 * s[3] + s[4];
                        E43   += E3 * s[1] + s[2];
                        E3 += s[0];  E4 += s[1];  S5t += s[3];
                    }
                    Y0acc += W543t;
                    float* wp = g_W + ((size_t)(b * 64 + tid) * NCH + c) * WSTRIDE;
                    wp[8]=E3; wp[9]=E4; wp[10]=E43; wp[2]=S5t; wp[4]=W54t;
                }
            } else {
                float e6=0.f,e7=0.f,e8=0.f,e76=0.f,e87=0.f,e876=0.f;
                float S9=0.f,W98=0.f,W987=0.f,W9876=0.f;
#pragma unroll 4
                for (int i = 0; i < 16; i++) {
                    const float* p = sP + (size_t)(r0 + i) * PSTR + u;
                    float m6 = p[0], m7 = p[64], m8 = p[128], m9 = p[192];
                    W98   = fmaf(m9, e8,   W98);
                    W987  = fmaf(m9, e87,  W987);
                    W9876 = fmaf(m9, e876, W9876);  S9 += m9;
                    e876  = fmaf(m8, e76,  e876);
                    e87   = fmaf(m8, e7,   e87);
                    e76   = fmaf(m7, e6,   e76);
                    e6 += m6;  e7 += m7;  e8 += m8;
                }
                mp[0]=e6; mp[1]=e7; mp[2]=e8; mp[3]=e76; mp[4]=e87;
                mp[5]=e876; mp[6]=S9; mp[7]=W98; mp[8]=W987; mp[9]=W9876;
                __syncthreads();
                if (tid < 64) {
                    float E6=0.f,E7=0.f,E8=0.f,E76=0.f,E87=0.f,E876=0.f;
                    float S9t=0.f,W98t=0.f,W987t=0.f,W9876t=0.f;
#pragma unroll
                    for (int q = 0; q < 4; q++) {
                        const float* s = sMaps + (size_t)(q * 64 + tid) * 10;
                        W9876t += E876 * s[6] + E76 * s[7] + E6 * s[8] + s[9];
                        W987t  += E87 * s[6] + E7 * s[7] + s[8];
                        W98t   += E8 * s[6] + s[7];
                        E876   += E76 * s[2] + E6 * s[4] + s[5];
                        E87    += E7 * s[2] + s[4];
                        E76    += E6 * s[1] + s[3];
                        E6 += s[0];  E7 += s[1];  E8 += s[2];  S9t += s[6];
                    }
                    Y0acc += W9876t;
                    float* wp = g_W + ((size_t)(b * 64 + tid) * NCH + c) * WSTRIDE;
                    wp[11]=E6; wp[12]=E7; wp[13]=E76; wp[14]=E8; wp[15]=E87;
                    wp[16]=E876; wp[3]=S9t; wp[5]=W98t; wp[6]=W987t;
                    wp[0]=Y0acc;
                }
            }
        }
    }
}

// ---------------- Combine: warp-tree composition over 32 chunks ----------------
__device__ __forceinline__ SigMap sig_shfl_down(const SigMap& m, int o) {
    SigMap r;
    r.Y0  = __shfl_down_sync(0xffffffffu, m.Y0,  o);
    r.S2  = __shfl_down_sync(0xffffffffu, m.S2,  o);
    r.S5  = __shfl_down_sync(0xffffffffu, m.S5,  o);
    r.S9  = __shfl_down_sync(0xffffffffu, m.S9,  o);
    r.W54 = __shfl_down_sync(0xffffffffu, m.W54, o);
    r.W98 = __shfl_down_sync(0xffffffffu, m.W98, o);
    r.W987= __shfl_down_sync(0xffffffffu, m.W987,o);
    r.E1  = __shfl_down_sync(0xffffffffu, m.E1,  o);
    r.E3  = __shfl_down_sync(0xffffffffu, m.E3,  o);
    r.E4  = __shfl_down_sync(0xffffffffu, m.E4,  o);
    r.E43 = __shfl_down_sync(0xffffffffu, m.E43, o);
    r.E6  = __shfl_down_sync(0xffffffffu, m.E6,  o);
    r.E7  = __shfl_down_sync(0xffffffffu, m.E7,  o);
    r.E76 = __shfl_down_sync(0xffffffffu, m.E76, o);
    r.E8  = __shfl_down_sync(0xffffffffu, m.E8,  o);
    r.E87 = __shfl_down_sync(0xffffffffu, m.E87, o);
    r.E876= __shfl_down_sync(0xffffffffu, m.E876,o);
    return r;
}

extern "C" __global__ void __launch_bounds__(256)
lrsig_combine(float* __restrict__ out)
{
    const int chain = blockIdx.x * 8 + (threadIdx.x >> 5);
    const int lane  = threadIdx.x & 31;

    // 4x LDG.128 + 1x LDG.32 per lane (record is 80B, 16B-aligned)
    const float4* wq = reinterpret_cast<const float4*>(
        g_W + ((size_t)chain * NCH + lane) * WSTRIDE);
    float4 q0 = wq[0], q1 = wq[1], q2 = wq[2], q3 = wq[3];
    float  e876 = reinterpret_cast<const float*>(wq)[16];

    SigMap M;
    M.Y0  = q0.x;  M.S2  = q0.y;  M.S5  = q0.z;  M.S9  = q0.w;
    M.W54 = q1.x;  M.W98 = q1.y;  M.W987= q1.z;  M.E1  = q1.w;
    M.E3  = q2.x;  M.E4  = q2.y;  M.E43 = q2.z;  M.E6  = q2.w;
    M.E7  = q3.x;  M.E76 = q3.y;  M.E8  = q3.z;  M.E87 = q3.w;
    M.E876= e876;

#pragma unroll
    for (int o = 1; o < 32; o <<= 1)
        M = sig_compose(M, sig_shfl_down(M, o));   // lane 0 exact after tree

    if (lane == 0) out[chain] = M.Y0;   // initial state zero -> Y = Y0
}

// ---------------- Launch ----------------
extern "C" void kernel_launch(void* const* d_in, const int* in_sizes, int n_in,
                              void* d_out, int out_size)
{
    const float* x    = (const float*)d_in[0];  // (32, 2048, 63) f32
    const float* kern = (const float*)d_in[1];  // (64, 10, 64)  f32

    cudaFuncSetAttribute(lrsig_fused, cudaFuncAttributeMaxDynamicSharedMemorySize,
                         SMEM_TOTAL);

    lrsig_prep<<<(FDIM * LUDIM + 255) / 256, 256>>>(kern);
    lrsig_fused<<<dim3(NCH, BB), 256, SMEM_TOTAL>>>(x, kern);
    lrsig_combine<<<NCHAIN / 8, 256>>>((float*)d_out);
}

// round 15
// speedup vs baseline: 1.0672x; 1.0672x over previous
#include <cuda_runtime.h>
#include <cuda_fp16.h>
#include <cstdint>
#include <cstddef>

// Problem constants
#define BB     32
#define TT     2048
#define FIN    63
#define FDIM   64
#define LUDIM  640
#define NCH    32      // chunks of 64 timesteps
#define TCH    64
#define NCHAIN 2048

// smem layout — total 104,448 B -> 2 CTAs/SM
#define XSTR   72      // Xh row stride (fp16 elems)
#define KSTR   72      // K stage stride (fp16 elems): 64 cols + 8 pad (144 B/row)
#define PSTR   260     // sP row stride (floats)
#define OFF_XH 0               // 64*72*2 = 9216
#define OFF_KH 9216            // 9216
#define OFF_KL 18432           // 9216
#define OFF_MAPS 27648         // 4*64*10*4 = 10240
#define OFF_SP 37888
#define SMEM_TOTAL (OFF_SP + TCH * PSTR * 4)   // 37888 + 66560 = 104448

#define WSTRIDE 20     // g_W record stride (floats), 80 B, 16B-aligned

// g_W layout: [chain][c][20]
__device__ float g_W[(size_t)NCHAIN * NCH * WSTRIDE];

// ---------------- PTX helpers ----------------
__device__ __forceinline__ uint32_t smem_u32(const void* p) {
    uint32_t a;
    asm("{ .reg .u64 t; cvta.to.shared.u64 t, %1; cvt.u32.u64 %0, t; }" : "=r"(a) : "l"(p));
    return a;
}
__device__ __forceinline__ void ldsm_x4(uint32_t& r0, uint32_t& r1, uint32_t& r2, uint32_t& r3,
                                        uint32_t addr) {
    asm volatile("ldmatrix.sync.aligned.m8n8.x4.shared.b16 {%0,%1,%2,%3}, [%4];"
                 : "=r"(r0), "=r"(r1), "=r"(r2), "=r"(r3) : "r"(addr));
}
__device__ __forceinline__ void ldsm_x4t(uint32_t& r0, uint32_t& r1, uint32_t& r2, uint32_t& r3,
                                         uint32_t addr) {
    asm volatile("ldmatrix.sync.aligned.m8n8.x4.trans.shared.b16 {%0,%1,%2,%3}, [%4];"
                 : "=r"(r0), "=r"(r1), "=r"(r2), "=r"(r3) : "r"(addr));
}
__device__ __forceinline__ void mma_f16(float* c, const uint32_t* a, uint32_t b0, uint32_t b1) {
    asm volatile(
        "mma.sync.aligned.m16n8k16.row.col.f32.f16.f16.f32 "
        "{%0,%1,%2,%3}, {%4,%5,%6,%7}, {%8,%9}, {%0,%1,%2,%3};"
        : "+f"(c[0]), "+f"(c[1]), "+f"(c[2]), "+f"(c[3])
        : "r"(a[0]), "r"(a[1]), "r"(a[2]), "r"(a[3]), "r"(b0), "r"(b1));
}
__device__ __forceinline__ uint32_t pack_h2(__half a, __half b) {
    __half2 h = __halves2half2(a, b);
    return *reinterpret_cast<uint32_t*>(&h);
}

// ---------------- Chen map (combine kernel) ----------------
struct SigMap {
    float Y0,S2,S5,S9,W54,W98,W987,E1,E3,E4,E43,E6,E7,E76,E8,E87,E876;
};

__device__ __forceinline__ SigMap sig_compose(const SigMap& A, const SigMap& B) {
    SigMap C;
    C.E1   = A.E1 + B.E1;
    C.E3   = A.E3 + B.E3;
    C.E6   = A.E6 + B.E6;
    C.E4   = A.E4 + B.E4;
    C.E43  = A.E43 + A.E3 * B.E4 + B.E43;
    C.E7   = A.E7 + B.E7;
    C.E76  = A.E76 + A.E6 * B.E7 + B.E76;
    C.E8   = A.E8 + B.E8;
    C.E87  = A.E87 + A.E7 * B.E8 + B.E87;
    C.E876 = A.E876 + A.E76 * B.E8 + A.E6 * B.E87 + B.E876;
    C.S2   = A.S2 + B.S2;
    C.S5   = A.S5 + B.S5;
    C.S9   = A.S9 + B.S9;
    C.W54  = A.W54 + A.E4 * B.S5 + B.W54;
    C.W98  = A.W98 + A.E8 * B.S9 + B.W98;
    C.W987 = A.W987 + A.E87 * B.S9 + A.E7 * B.W98 + B.W987;
    C.Y0   = A.Y0 + B.Y0 + A.E1 * B.S2 + A.E43 * B.S5 + A.E3 * B.W54
           + A.E876 * B.S9 + A.E76 * B.W98 + A.E6 * B.W987;
    return C;
}

// ---------------- Fused kernel: m = dX @ K (fp16 2-term) + 3-pass scan ----------------
// Grid (NCH, BB) = (32, 32), 256 threads, 2 CTAs/SM.
// m = Xh·Kh + Xh·Kl: X quantized to fp16 once (error random in t -> cancels);
// K split hi/lo fp16 (exact to ~2^-22). 32 MMA/warp/stage (was 48).
// K loaded as fp32 from gmem and split in registers (prep kernel deleted).
extern "C" __global__ void __launch_bounds__(256, 2)
lrsig_fused(const float* __restrict__ x, const float* __restrict__ kern)
{
    extern __shared__ char smem[];
    float* sP    = reinterpret_cast<float*>(smem + OFF_SP);
    float* sMaps = reinterpret_cast<float*>(smem + OFF_MAPS);
    const uint32_t sb = smem_u32(smem);

    const int tid  = threadIdx.x;
    const int lane = tid & 31;
    const int w    = tid >> 5;
    const int wt   = w & 3;
    const int wn   = w >> 2;
    const int c    = blockIdx.x;
    const int b    = blockIdx.y;
    const int t0   = c * TCH;

    // K prefetch: stage = 64 f-rows x 16 fp32-uint4 = 1024 uint4, 4 per thread.
    // v = uint4-col (0..15), rows f = fb + 16r, r = 0..3.
    const uint4* kernF4 = reinterpret_cast<const uint4*>(kern);   // 160 uint4/row
    const int v  = tid & 15;
    const int fb = tid >> 4;

    // Prefetch stage 0 (overlaps dX fill)
    uint4 kf[4];
#pragma unroll
    for (int r = 0; r < 4; r++)
        kf[r] = kernF4[(fb + 16 * r) * 160 + v];

    // ---- Xh tile (fp16), [t][f], stride 72; exact fp32 diff then 1 cvt ----
    for (int e = tid; e < TCH * FDIM; e += 256) {
        int tl = e >> 6, f = e & 63;
        int t = t0 + tl;
        float vv;
        if (t == 0)      vv = 0.0f;                                  // m[0] = 0
        else if (f < FIN) {
            const float* xr = x + ((size_t)b * TT + t) * FIN + f;
            vv = xr[0] - xr[-FIN];
        } else            vv = 2.0f / 2047.0f;                       // d(time)
        *reinterpret_cast<__half*>(smem + OFF_XH + (tl * XSTR + f) * 2) =
            __float2half_rn(vv);
    }
    __syncthreads();

    // ---- Preload A fragments once (16 regs; reused across all 10 stages) ----
    const uint32_t a_off = (uint32_t)((lane & 15) * XSTR + ((lane >> 4) << 3)) * 2;
    uint32_t Ah[4][4];
#pragma unroll
    for (int ks = 0; ks < 4; ks++) {
        uint32_t ra = (uint32_t)(wt * 16 * XSTR + ks * 16) * 2 + a_off;
        ldsm_x4(Ah[ks][0], Ah[ks][1], Ah[ks][2], Ah[ks][3], sb + OFF_XH + ra);
    }

    // Commit helper data
    const uint32_t b_off = (uint32_t)((((lane >> 3) & 1) * 8 + (lane & 7)) * KSTR
                                      + ((lane >> 4) << 3)) * 2;

    // Commit stage 0: split fp32 -> (hi, lo) fp16, STS.64 per quad
#pragma unroll
    for (int r = 0; r < 4; r++) {
        float4 f4 = *reinterpret_cast<float4*>(&kf[r]);
        __half hx = __float2half_rn(f4.x), hy = __float2half_rn(f4.y);
        __half hz = __float2half_rn(f4.z), hw = __float2half_rn(f4.w);
        __half lx = __float2half_rn(f4.x - __half2float(hx));
        __half ly = __float2half_rn(f4.y - __half2float(hy));
        __half lz = __float2half_rn(f4.z - __half2float(hz));
        __half lw = __float2half_rn(f4.w - __half2float(hw));
        int off = (fb + 16 * r) * 144 + v * 8;
        *reinterpret_cast<uint2*>(smem + OFF_KH + off) =
            make_uint2(pack_h2(hx, hy), pack_h2(hz, hw));
        *reinterpret_cast<uint2*>(smem + OFF_KL + off) =
            make_uint2(pack_h2(lx, ly), pack_h2(lz, lw));
    }
    __syncthreads();   // K stage 0 ready (A frags already in regs)

    float Y0acc = 0.0f;

    // ---- Stage loop: 10 stages of 64 cols; single K buffer, 2 syncs/stage ----
    for (int j = 0; j < 10; j++) {
        // Prefetch K fp32 for stage j+1 (overlaps this stage's MMA)
        if (j < 9) {
#pragma unroll
            for (int r = 0; r < 4; r++)
                kf[r] = kernF4[(fb + 16 * r) * 160 + (j + 1) * 16 + v];
        }

        float C[4][4];
#pragma unroll
        for (int nt = 0; nt < 4; nt++)
#pragma unroll
            for (int i = 0; i < 4; i++) C[nt][i] = 0.0f;

#pragma unroll
        for (int ks = 0; ks < 4; ks++)
#pragma unroll
            for (int q = 0; q < 2; q++) {
                uint32_t rb = (uint32_t)(ks * 16 * KSTR + (wn * 32 + q * 16)) * 2 + b_off;
                uint32_t Bh[4], Bl[4];
                ldsm_x4t(Bh[0], Bh[1], Bh[2], Bh[3], sb + OFF_KH + rb);
                ldsm_x4t(Bl[0], Bl[1], Bl[2], Bl[3], sb + OFF_KL + rb);
#pragma unroll
                for (int p = 0; p < 2; p++) {
                    float* cc = C[q * 2 + p];
                    mma_f16(cc, Ah[ks], Bh[p * 2], Bh[p * 2 + 1]);
                    mma_f16(cc, Ah[ks], Bl[p * 2], Bl[p * 2 + 1]);
                }
            }

        // Epilogue into sP at pass-local columns
        {
            const int ps = (j < 3) ? 0 : ((j < 6) ? 3 : 6);
            const int cb = (j - ps) * 64;
            int r = wt * 16 + (lane >> 2);
#pragma unroll
            for (int nt = 0; nt < 4; nt++) {
                int col = cb + wn * 32 + nt * 8 + (lane & 3) * 2;
                float* q0 = sP + (size_t)r * PSTR + col;
                float* q1 = sP + (size_t)(r + 8) * PSTR + col;
                *reinterpret_cast<float2*>(q0) = make_float2(C[nt][0], C[nt][1]);
                *reinterpret_cast<float2*>(q1) = make_float2(C[nt][2], C[nt][3]);
            }
        }

        // ---- Pass-end scans ----
        if (j == 2 || j == 5 || j == 9) {
            __syncthreads();     // sP complete for this pass
            const int u  = tid & 63;
            const int qc = tid >> 6;        // 0..3, 16 rows each
            const int r0 = qc * 16;
            float* mp = sMaps + (size_t)(qc * 64 + u) * 10;

            if (j == 2) {
                float y0 = 0.f, e1 = 0.f, S2 = 0.f, W21 = 0.f;
#pragma unroll 4
                for (int i = 0; i < 16; i++) {
                    const float* p = sP + (size_t)(r0 + i) * PSTR + u;
                    float m0 = p[0], m1 = p[64], m2 = p[128];
                    y0 += m0;
                    W21 = fmaf(m2, e1, W21);  S2 += m2;  e1 += m1;
                }
                mp[0] = y0; mp[1] = e1; mp[2] = S2; mp[3] = W21;
                __syncthreads();
                if (tid < 64) {
                    float Y = 0.f, E1 = 0.f, S2t = 0.f, W21t = 0.f;
#pragma unroll
                    for (int q = 0; q < 4; q++) {
                        const float* s = sMaps + (size_t)(q * 64 + tid) * 10;
                        W21t += E1 * s[2] + s[3];
                        E1   += s[1];  S2t += s[2];  Y += s[0];
                    }
                    Y0acc = Y + W21t;
                    float* wp = g_W + ((size_t)(b * 64 + tid) * NCH + c) * WSTRIDE;
                    wp[7] = E1;  wp[1] = S2t;
                }
            } else if (j == 5) {
                float e3=0.f,e4=0.f,e43=0.f,S5=0.f,W54=0.f,W543=0.f;
#pragma unroll 4
                for (int i = 0; i < 16; i++) {
                    const float* p = sP + (size_t)(r0 + i) * PSTR + u;
                    float m3 = p[0], m4 = p[64], m5 = p[128];
                    W54  = fmaf(m5, e4,  W54);
                    W543 = fmaf(m5, e43, W543);  S5 += m5;
                    e43  = fmaf(m4, e3,  e43);
                    e3 += m3;  e4 += m4;
                }
                mp[0]=e3; mp[1]=e4; mp[2]=e43; mp[3]=S5; mp[4]=W54; mp[5]=W543;
                __syncthreads();
                if (tid < 64) {
                    float E3=0.f,E4=0.f,E43=0.f,S5t=0.f,W54t=0.f,W543t=0.f;
#pragma unroll
                    for (int q = 0; q < 4; q++) {
                        const float* s = sMaps + (size_t)(q * 64 + tid) * 10;
                        W543t += E43 * s[3] + E3 * s[4] + s[5];
                        W54t  += E4 * s[3] + s[4];
                        E43   += E3 * s[1] + s[2];
                        E3 += s[0];  E4 += s[1];  S5t += s[3];
                    }
                    Y0acc += W543t;
                    float* wp = g_W + ((size_t)(b * 64 + tid) * NCH + c) * WSTRIDE;
                    wp[8]=E3; wp[9]=E4; wp[10]=E43; wp[2]=S5t; wp[4]=W54t;
                }
            } else {
                float e6=0.f,e7=0.f,e8=0.f,e76=0.f,e87=0.f,e876=0.f;
                float S9=0.f,W98=0.f,W987=0.f,W9876=0.f;
#pragma unroll 4
                for (int i = 0; i < 16; i++) {
                    const float* p = sP + (size_t)(r0 + i) * PSTR + u;
                    float m6 = p[0], m7 = p[64], m8 = p[128], m9 = p[192];
                    W98   = fmaf(m9, e8,   W98);
                    W987  = fmaf(m9, e87,  W987);
                    W9876 = fmaf(m9, e876, W9876);  S9 += m9;
                    e876  = fmaf(m8, e76,  e876);
                    e87   = fmaf(m8, e7,   e87);
                    e76   = fmaf(m7, e6,   e76);
                    e6 += m6;  e7 += m7;  e8 += m8;
                }
                mp[0]=e6; mp[1]=e7; mp[2]=e8; mp[3]=e76; mp[4]=e87;
                mp[5]=e876; mp[6]=S9; mp[7]=W98; mp[8]=W987; mp[9]=W9876;
                __syncthreads();
                if (tid < 64) {
                    float E6=0.f,E7=0.f,E8=0.f,E76=0.f,E87=0.f,E876=0.f;
                    float S9t=0.f,W98t=0.f,W987t=0.f,W9876t=0.f;
#pragma unroll
                    for (int q = 0; q < 4; q++) {
                        const float* s = sMaps + (size_t)(q * 64 + tid) * 10;
                        W9876t += E876 * s[6] + E76 * s[7] + E6 * s[8] + s[9];
                        W987t  += E87 * s[6] + E7 * s[7] + s[8];
                        W98t   += E8 * s[6] + s[7];
                        E876   += E76 * s[2] + E6 * s[4] + s[5];
                        E87    += E7 * s[2] + s[4];
                        E76    += E6 * s[1] + s[3];
                        E6 += s[0];  E7 += s[1];  E8 += s[2];  S9t += s[6];
                    }
                    Y0acc += W9876t;
                    float* wp = g_W + ((size_t)(b * 64 + tid) * NCH + c) * WSTRIDE;
                    wp[11]=E6; wp[12]=E7; wp[13]=E76; wp[14]=E8; wp[15]=E87;
                    wp[16]=E876; wp[3]=S9t; wp[5]=W98t; wp[6]=W987t;
                    wp[0]=Y0acc;
                }
            }
        }

        // ---- Commit K stage j+1 (single buffer: sync, STS, sync) ----
        if (j < 9) {
            __syncthreads();   // all ldsm reads of stage j complete
#pragma unroll
            for (int r = 0; r < 4; r++) {
                float4 f4 = *reinterpret_cast<float4*>(&kf[r]);
                __half hx = __float2half_rn(f4.x), hy = __float2half_rn(f4.y);
                __half hz = __float2half_rn(f4.z), hw = __float2half_rn(f4.w);
                __half lx = __float2half_rn(f4.x - __half2float(hx));
                __half ly = __float2half_rn(f4.y - __half2float(hy));
                __half lz = __float2half_rn(f4.z - __half2float(hz));
                __half lw = __float2half_rn(f4.w - __half2float(hw));
                int off = (fb + 16 * r) * 144 + v * 8;
                *reinterpret_cast<uint2*>(smem + OFF_KH + off) =
                    make_uint2(pack_h2(hx, hy), pack_h2(hz, hw));
                *reinterpret_cast<uint2*>(smem + OFF_KL + off) =
                    make_uint2(pack_h2(lx, ly), pack_h2(lz, lw));
            }
            __syncthreads();   // K stage j+1 ready
        }
    }
}

// ---------------- Combine: warp-tree composition over 32 chunks ----------------
__device__ __forceinline__ SigMap sig_shfl_down(const SigMap& m, int o) {
    SigMap r;
    r.Y0  = __shfl_down_sync(0xffffffffu, m.Y0,  o);
    r.S2  = __shfl_down_sync(0xffffffffu, m.S2,  o);
    r.S5  = __shfl_down_sync(0xffffffffu, m.S5,  o);
    r.S9  = __shfl_down_sync(0xffffffffu, m.S9,  o);
    r.W54 = __shfl_down_sync(0xffffffffu, m.W54, o);
    r.W98 = __shfl_down_sync(0xffffffffu, m.W98, o);
    r.W987= __shfl_down_sync(0xffffffffu, m.W987,o);
    r.E1  = __shfl_down_sync(0xffffffffu, m.E1,  o);
    r.E3  = __shfl_down_sync(0xffffffffu, m.E3,  o);
    r.E4  = __shfl_down_sync(0xffffffffu, m.E4,  o);
    r.E43 = __shfl_down_sync(0xffffffffu, m.E43, o);
    r.E6  = __shfl_down_sync(0xffffffffu, m.E6,  o);
    r.E7  = __shfl_down_sync(0xffffffffu, m.E7,  o);
    r.E76 = __shfl_down_sync(0xffffffffu, m.E76, o);
    r.E8  = __shfl_down_sync(0xffffffffu, m.E8,  o);
    r.E87 = __shfl_down_sync(0xffffffffu, m.E87, o);
    r.E876= __shfl_down_sync(0xffffffffu, m.E876,o);
    return r;
}

extern "C" __global__ void __launch_bounds__(256)
lrsig_combine(float* __restrict__ out)
{
    const int chain = blockIdx.x * 8 + (threadIdx.x >> 5);
    const int lane  = threadIdx.x & 31;

    const float4* wq = reinterpret_cast<const float4*>(
        g_W + ((size_t)chain * NCH + lane) * WSTRIDE);
    float4 q0 = wq[0], q1 = wq[1], q2 = wq[2], q3 = wq[3];
    float  e876 = reinterpret_cast<const float*>(wq)[16];

    SigMap M;
    M.Y0  = q0.x;  M.S2  = q0.y;  M.S5  = q0.z;  M.S9  = q0.w;
    M.W54 = q1.x;  M.W98 = q1.y;  M.W987= q1.z;  M.E1  = q1.w;
    M.E3  = q2.x;  M.E4  = q2.y;  M.E43 = q2.z;  M.E6  = q2.w;
    M.E7  = q3.x;  M.E76 = q3.y;  M.E8  = q3.z;  M.E87 = q3.w;
    M.E876= e876;

#pragma unroll
    for (int o = 1; o < 32; o <<= 1)
        M = sig_compose(M, sig_shfl_down(M, o));   // lane 0 exact after tree

    if (lane == 0) out[chain] = M.Y0;   // initial state zero -> Y = Y0
}

// ---------------- Launch ----------------
extern "C" void kernel_launch(void* const* d_in, const int* in_sizes, int n_in,
                              void* d_out, int out_size)
{
    const float* x    = (const float*)d_in[0];  // (32, 2048, 63) f32
    const float* kern = (const float*)d_in[1];  // (64, 10, 64)  f32

    cudaFuncSetAttribute(lrsig_fused, cudaFuncAttributeMaxDynamicSharedMemorySize,
                         SMEM_TOTAL);

    lrsig_fused<<<dim3(NCH, BB), 256, SMEM_TOTAL>>>(x, kern);
    lrsig_combine<<<NCHAIN / 8, 256>>>((float*)d_out);
}

// round 16
// speedup vs baseline: 1.2058x; 1.1299x over previous
#include <cuda_runtime.h>
#include <cuda_fp16.h>
#include <cstdint>
#include <cstddef>

// Problem constants
#define BB     32
#define TT     2048
#define FIN    63
#define FDIM   64
#define LUDIM  640
#define NCH    32      // chunks of 64 timesteps
#define TCH    64
#define NCHAIN 2048

// smem layout — total 104,448 B -> 2 CTAs/SM
#define XSTR   72      // Xh row stride (fp16 elems)
#define KSTR   72      // K stage stride (fp16 elems): 64 cols + 8 pad (144 B/row)
#define PSTR   260     // sP row stride (floats)
#define OFF_XH 0               // 64*72*2 = 9216
#define OFF_KH 9216
#define OFF_KL 18432
#define OFF_MAPS 27648         // 4*64*10*4 = 10240
#define OFF_SP 37888
#define SMEM_TOTAL (OFF_SP + TCH * PSTR * 4)   // 104448

#define WSTRIDE 20     // g_W record stride (floats), 80 B, 16B-aligned

// g_W layout: [chain][c][20]
__device__ float g_W[(size_t)NCHAIN * NCH * WSTRIDE];

// ---------------- PTX helpers ----------------
__device__ __forceinline__ uint32_t smem_u32(const void* p) {
    uint32_t a;
    asm("{ .reg .u64 t; cvta.to.shared.u64 t, %1; cvt.u32.u64 %0, t; }" : "=r"(a) : "l"(p));
    return a;
}
__device__ __forceinline__ void ldsm_x4(uint32_t& r0, uint32_t& r1, uint32_t& r2, uint32_t& r3,
                                        uint32_t addr) {
    asm volatile("ldmatrix.sync.aligned.m8n8.x4.shared.b16 {%0,%1,%2,%3}, [%4];"
                 : "=r"(r0), "=r"(r1), "=r"(r2), "=r"(r3) : "r"(addr));
}
__device__ __forceinline__ void ldsm_x4t(uint32_t& r0, uint32_t& r1, uint32_t& r2, uint32_t& r3,
                                         uint32_t addr) {
    asm volatile("ldmatrix.sync.aligned.m8n8.x4.trans.shared.b16 {%0,%1,%2,%3}, [%4];"
                 : "=r"(r0), "=r"(r1), "=r"(r2), "=r"(r3) : "r"(addr));
}
__device__ __forceinline__ void mma_f16(float* c, const uint32_t* a, uint32_t b0, uint32_t b1) {
    asm volatile(
        "mma.sync.aligned.m16n8k16.row.col.f32.f16.f16.f32 "
        "{%0,%1,%2,%3}, {%4,%5,%6,%7}, {%8,%9}, {%0,%1,%2,%3};"
        : "+f"(c[0]), "+f"(c[1]), "+f"(c[2]), "+f"(c[3])
        : "r"(a[0]), "r"(a[1]), "r"(a[2]), "r"(a[3]), "r"(b0), "r"(b1));
}
__device__ __forceinline__ uint32_t pack_h2(__half a, __half b) {
    __half2 h = __halves2half2(a, b);
    return *reinterpret_cast<uint32_t*>(&h);
}

// ---------------- Chen map (combine kernel) ----------------
struct SigMap {
    float Y0,S2,S5,S9,W54,W98,W987,E1,E3,E4,E43,E6,E7,E76,E8,E87,E876;
};

__device__ __forceinline__ SigMap sig_compose(const SigMap& A, const SigMap& B) {
    SigMap C;
    C.E1   = A.E1 + B.E1;
    C.E3   = A.E3 + B.E3;
    C.E6   = A.E6 + B.E6;
    C.E4   = A.E4 + B.E4;
    C.E43  = A.E43 + A.E3 * B.E4 + B.E43;
    C.E7   = A.E7 + B.E7;
    C.E76  = A.E76 + A.E6 * B.E7 + B.E76;
    C.E8   = A.E8 + B.E8;
    C.E87  = A.E87 + A.E7 * B.E8 + B.E87;
    C.E876 = A.E876 + A.E76 * B.E8 + A.E6 * B.E87 + B.E876;
    C.S2   = A.S2 + B.S2;
    C.S5   = A.S5 + B.S5;
    C.S9   = A.S9 + B.S9;
    C.W54  = A.W54 + A.E4 * B.S5 + B.W54;
    C.W98  = A.W98 + A.E8 * B.S9 + B.W98;
    C.W987 = A.W987 + A.E87 * B.S9 + A.E7 * B.W98 + B.W987;
    C.Y0   = A.Y0 + B.Y0 + A.E1 * B.S2 + A.E43 * B.S5 + A.E3 * B.W54
           + A.E876 * B.S9 + A.E76 * B.W98 + A.E6 * B.W987;
    return C;
}

// ---------------- Fused kernel: m = dX @ K (fp16 2-term) + 3-pass scan ----------------
// Grid (NCH, BB) = (32, 32), 256 threads, 2 CTAs/SM.
// Warp tile m32 x n16 (wt = w&1, wn = w>>1): B fragments shared by only 2
// warps (was 4) -> B ldsm per warp-stage halves (16 -> 8 x4t ops).
extern "C" __global__ void __launch_bounds__(256, 2)
lrsig_fused(const float* __restrict__ x, const float* __restrict__ kern)
{
    extern __shared__ char smem[];
    float* sP    = reinterpret_cast<float*>(smem + OFF_SP);
    float* sMaps = reinterpret_cast<float*>(smem + OFF_MAPS);
    const uint32_t sb = smem_u32(smem);

    const int tid  = threadIdx.x;
    const int lane = tid & 31;
    const int w    = tid >> 5;
    const int wt   = w & 1;        // 32-row half
    const int wn   = w >> 1;       // 16-col group (4 groups = 64-col stage)
    const int c    = blockIdx.x;
    const int b    = blockIdx.y;
    const int t0   = c * TCH;

    // K prefetch: stage = 64 f-rows x 16 fp32-uint4 = 1024 uint4, 4 per thread.
    const uint4* kernF4 = reinterpret_cast<const uint4*>(kern);   // 160 uint4/row
    const int v  = tid & 15;
    const int fb = tid >> 4;

    // Prefetch stage 0 (overlaps dX fill)
    uint4 kf[4];
#pragma unroll
    for (int r = 0; r < 4; r++)
        kf[r] = kernF4[(fb + 16 * r) * 160 + v];

    // ---- Xh tile (fp16), [t][f], stride 72; exact fp32 diff then 1 cvt ----
    for (int e = tid; e < TCH * FDIM; e += 256) {
        int tl = e >> 6, f = e & 63;
        int t = t0 + tl;
        float vv;
        if (t == 0)      vv = 0.0f;                                  // m[0] = 0
        else if (f < FIN) {
            const float* xr = x + ((size_t)b * TT + t) * FIN + f;
            vv = xr[0] - xr[-FIN];
        } else            vv = 2.0f / 2047.0f;                       // d(time)
        *reinterpret_cast<__half*>(smem + OFF_XH + (tl * XSTR + f) * 2) =
            __float2half_rn(vv);
    }
    __syncthreads();

    // ---- Preload A fragments once (m32: 2 mt-tiles x 4 ks = 32 regs) ----
    const uint32_t a_off = (uint32_t)((lane & 15) * XSTR + ((lane >> 4) << 3)) * 2;
    uint32_t Ah[2][4][4];
#pragma unroll
    for (int mt = 0; mt < 2; mt++)
#pragma unroll
        for (int ks = 0; ks < 4; ks++) {
            uint32_t ra = (uint32_t)((wt * 32 + mt * 16) * XSTR + ks * 16) * 2 + a_off;
            ldsm_x4(Ah[mt][ks][0], Ah[mt][ks][1], Ah[mt][ks][2], Ah[mt][ks][3],
                    sb + OFF_XH + ra);
        }

    const uint32_t b_off = (uint32_t)((((lane >> 3) & 1) * 8 + (lane & 7)) * KSTR
                                      + ((lane >> 4) << 3)) * 2;

    // Commit stage 0: split fp32 -> (hi, lo) fp16
#pragma unroll
    for (int r = 0; r < 4; r++) {
        float4 f4 = *reinterpret_cast<float4*>(&kf[r]);
        __half hx = __float2half_rn(f4.x), hy = __float2half_rn(f4.y);
        __half hz = __float2half_rn(f4.z), hw = __float2half_rn(f4.w);
        __half lx = __float2half_rn(f4.x - __half2float(hx));
        __half ly = __float2half_rn(f4.y - __half2float(hy));
        __half lz = __float2half_rn(f4.z - __half2float(hz));
        __half lw = __float2half_rn(f4.w - __half2float(hw));
        int off = (fb + 16 * r) * 144 + v * 8;
        *reinterpret_cast<uint2*>(smem + OFF_KH + off) =
            make_uint2(pack_h2(hx, hy), pack_h2(hz, hw));
        *reinterpret_cast<uint2*>(smem + OFF_KL + off) =
            make_uint2(pack_h2(lx, ly), pack_h2(lz, lw));
    }
    __syncthreads();   // K stage 0 ready

    float Y0acc = 0.0f;

    // ---- Stage loop: 10 stages of 64 cols ----
    for (int j = 0; j < 10; j++) {
        // Prefetch K fp32 for stage j+1 (overlaps this stage's MMA)
        if (j < 9) {
#pragma unroll
            for (int r = 0; r < 4; r++)
                kf[r] = kernF4[(fb + 16 * r) * 160 + (j + 1) * 16 + v];
        }

        float C[2][2][4];
#pragma unroll
        for (int mt = 0; mt < 2; mt++)
#pragma unroll
            for (int p = 0; p < 2; p++)
#pragma unroll
                for (int i = 0; i < 4; i++) C[mt][p][i] = 0.0f;

#pragma unroll
        for (int ks = 0; ks < 4; ks++) {
            // One n16 x k16 B tile per warp per ks (hi + lo): 2 ldsm.x4t
            uint32_t rb = (uint32_t)(ks * 16 * KSTR + wn * 16) * 2 + b_off;
            uint32_t Bh[4], Bl[4];
            ldsm_x4t(Bh[0], Bh[1], Bh[2], Bh[3], sb + OFF_KH + rb);
            ldsm_x4t(Bl[0], Bl[1], Bl[2], Bl[3], sb + OFF_KL + rb);
#pragma unroll
            for (int mt = 0; mt < 2; mt++)
#pragma unroll
                for (int p = 0; p < 2; p++) {
                    float* cc = C[mt][p];
                    mma_f16(cc, Ah[mt][ks], Bh[p * 2], Bh[p * 2 + 1]);
                    mma_f16(cc, Ah[mt][ks], Bl[p * 2], Bl[p * 2 + 1]);
                }
        }

        // Epilogue into sP at pass-local columns
        {
            const int ps = (j < 3) ? 0 : ((j < 6) ? 3 : 6);
            const int cb = (j - ps) * 64;
#pragma unroll
            for (int mt = 0; mt < 2; mt++) {
                int r = wt * 32 + mt * 16 + (lane >> 2);
#pragma unroll
                for (int p = 0; p < 2; p++) {
                    int col = cb + wn * 16 + p * 8 + (lane & 3) * 2;
                    float* q0 = sP + (size_t)r * PSTR + col;
                    float* q1 = sP + (size_t)(r + 8) * PSTR + col;
                    *reinterpret_cast<float2*>(q0) = make_float2(C[mt][p][0], C[mt][p][1]);
                    *reinterpret_cast<float2*>(q1) = make_float2(C[mt][p][2], C[mt][p][3]);
                }
            }
        }

        // ---- Pass-end scans ----
        if (j == 2 || j == 5 || j == 9) {
            __syncthreads();     // sP complete for this pass
            const int u  = tid & 63;
            const int qc = tid >> 6;        // 0..3, 16 rows each
            const int r0 = qc * 16;
            float* mp = sMaps + (size_t)(qc * 64 + u) * 10;

            if (j == 2) {
                float y0 = 0.f, e1 = 0.f, S2 = 0.f, W21 = 0.f;
#pragma unroll 4
                for (int i = 0; i < 16; i++) {
                    const float* p = sP + (size_t)(r0 + i) * PSTR + u;
                    float m0 = p[0], m1 = p[64], m2 = p[128];
                    y0 += m0;
                    W21 = fmaf(m2, e1, W21);  S2 += m2;  e1 += m1;
                }
                mp[0] = y0; mp[1] = e1; mp[2] = S2; mp[3] = W21;
                __syncthreads();
                if (tid < 64) {
                    float Y = 0.f, E1 = 0.f, S2t = 0.f, W21t = 0.f;
#pragma unroll
                    for (int q = 0; q < 4; q++) {
                        const float* s = sMaps + (size_t)(q * 64 + tid) * 10;
                        W21t += E1 * s[2] + s[3];
                        E1   += s[1];  S2t += s[2];  Y += s[0];
                    }
                    Y0acc = Y + W21t;
                    float* wp = g_W + ((size_t)(b * 64 + tid) * NCH + c) * WSTRIDE;
                    wp[7] = E1;  wp[1] = S2t;
                }
            } else if (j == 5) {
                float e3=0.f,e4=0.f,e43=0.f,S5=0.f,W54=0.f,W543=0.f;
#pragma unroll 4
                for (int i = 0; i < 16; i++) {
                    const float* p = sP + (size_t)(r0 + i) * PSTR + u;
                    float m3 = p[0], m4 = p[64], m5 = p[128];
                    W54  = fmaf(m5, e4,  W54);
                    W543 = fmaf(m5, e43, W543);  S5 += m5;
                    e43  = fmaf(m4, e3,  e43);
                    e3 += m3;  e4 += m4;
                }
                mp[0]=e3; mp[1]=e4; mp[2]=e43; mp[3]=S5; mp[4]=W54; mp[5]=W543;
                __syncthreads();
                if (tid < 64) {
                    float E3=0.f,E4=0.f,E43=0.f,S5t=0.f,W54t=0.f,W543t=0.f;
#pragma unroll
                    for (int q = 0; q < 4; q++) {
                        const float* s = sMaps + (size_t)(q * 64 + tid) * 10;
                        W543t += E43 * s[3] + E3 * s[4] + s[5];
                        W54t  += E4 * s[3] + s[4];
                        E43   += E3 * s[1] + s[2];
                        E3 += s[0];  E4 += s[1];  S5t += s[3];
                    }
                    Y0acc += W543t;
                    float* wp = g_W + ((size_t)(b * 64 + tid) * NCH + c) * WSTRIDE;
                    wp[8]=E3; wp[9]=E4; wp[10]=E43; wp[2]=S5t; wp[4]=W54t;
                }
            } else {
                float e6=0.f,e7=0.f,e8=0.f,e76=0.f,e87=0.f,e876=0.f;
                float S9=0.f,W98=0.f,W987=0.f,W9876=0.f;
#pragma unroll 4
                for (int i = 0; i < 16; i++) {
                    const float* p = sP + (size_t)(r0 + i) * PSTR + u;
                    float m6 = p[0], m7 = p[64], m8 = p[128], m9 = p[192];
                    W98   = fmaf(m9, e8,   W98);
                    W987  = fmaf(m9, e87,  W987);
                    W9876 = fmaf(m9, e876, W9876);  S9 += m9;
                    e876  = fmaf(m8, e76,  e876);
                    e87   = fmaf(m8, e7,   e87);
                    e76   = fmaf(m7, e6,   e76);
                    e6 += m6;  e7 += m7;  e8 += m8;
                }
                mp[0]=e6; mp[1]=e7; mp[2]=e8; mp[3]=e76; mp[4]=e87;
                mp[5]=e876; mp[6]=S9; mp[7]=W98; mp[8]=W987; mp[9]=W9876;
                __syncthreads();
                if (tid < 64) {
                    float E6=0.f,E7=0.f,E8=0.f,E76=0.f,E87=0.f,E876=0.f;
                    float S9t=0.f,W98t=0.f,W987t=0.f,W9876t=0.f;
#pragma unroll
                    for (int q = 0; q < 4; q++) {
                        const float* s = sMaps + (size_t)(q * 64 + tid) * 10;
                        W9876t += E876 * s[6] + E76 * s[7] + E6 * s[8] + s[9];
                        W987t  += E87 * s[6] + E7 * s[7] + s[8];
                        W98t   += E8 * s[6] + s[7];
                        E876   += E76 * s[2] + E6 * s[4] + s[5];
                        E87    += E7 * s[2] + s[4];
                        E76    += E6 * s[1] + s[3];
                        E6 += s[0];  E7 += s[1];  E8 += s[2];  S9t += s[6];
                    }
                    Y0acc += W9876t;
                    float* wp = g_W + ((size_t)(b * 64 + tid) * NCH + c) * WSTRIDE;
                    wp[11]=E6; wp[12]=E7; wp[13]=E76; wp[14]=E8; wp[15]=E87;
                    wp[16]=E876; wp[3]=S9t; wp[5]=W98t; wp[6]=W987t;
                    wp[0]=Y0acc;
                }
            }
        }

        // ---- Commit K stage j+1 ----
        if (j < 9) {
            __syncthreads();   // all ldsm reads of stage j complete
#pragma unroll
            for (int r = 0; r < 4; r++) {
                float4 f4 = *reinterpret_cast<float4*>(&kf[r]);
                __half hx = __float2half_rn(f4.x), hy = __float2half_rn(f4.y);
                __half hz = __float2half_rn(f4.z), hw = __float2half_rn(f4.w);
                __half lx = __float2half_rn(f4.x - __half2float(hx));
                __half ly = __float2half_rn(f4.y - __half2float(hy));
                __half lz = __float2half_rn(f4.z - __half2float(hz));
                __half lw = __float2half_rn(f4.w - __half2float(hw));
                int off = (fb + 16 * r) * 144 + v * 8;
                *reinterpret_cast<uint2*>(smem + OFF_KH + off) =
                    make_uint2(pack_h2(hx, hy), pack_h2(hz, hw));
                *reinterpret_cast<uint2*>(smem + OFF_KL + off) =
                    make_uint2(pack_h2(lx, ly), pack_h2(lz, lw));
            }
            __syncthreads();   // K stage j+1 ready
        }
    }
}

// ---------------- Combine: warp-tree composition over 32 chunks ----------------
__device__ __forceinline__ SigMap sig_shfl_down(const SigMap& m, int o) {
    SigMap r;
    r.Y0  = __shfl_down_sync(0xffffffffu, m.Y0,  o);
    r.S2  = __shfl_down_sync(0xffffffffu, m.S2,  o);
    r.S5  = __shfl_down_sync(0xffffffffu, m.S5,  o);
    r.S9  = __shfl_down_sync(0xffffffffu, m.S9,  o);
    r.W54 = __shfl_down_sync(0xffffffffu, m.W54, o);
    r.W98 = __shfl_down_sync(0xffffffffu, m.W98, o);
    r.W987= __shfl_down_sync(0xffffffffu, m.W987,o);
    r.E1  = __shfl_down_sync(0xffffffffu, m.E1,  o);
    r.E3  = __shfl_down_sync(0xffffffffu, m.E3,  o);
    r.E4  = __shfl_down_sync(0xffffffffu, m.E4,  o);
    r.E43 = __shfl_down_sync(0xffffffffu, m.E43, o);
    r.E6  = __shfl_down_sync(0xffffffffu, m.E6,  o);
    r.E7  = __shfl_down_sync(0xffffffffu, m.E7,  o);
    r.E76 = __shfl_down_sync(0xffffffffu, m.E76, o);
    r.E8  = __shfl_down_sync(0xffffffffu, m.E8,  o);
    r.E87 = __shfl_down_sync(0xffffffffu, m.E87, o);
    r.E876= __shfl_down_sync(0xffffffffu, m.E876,o);
    return r;
}

extern "C" __global__ void __launch_bounds__(256)
lrsig_combine(float* __restrict__ out)
{
    const int chain = blockIdx.x * 8 + (threadIdx.x >> 5);
    const int lane  = threadIdx.x & 31;

    const float4* wq = reinterpret_cast<const float4*>(
        g_W + ((size_t)chain * NCH + lane) * WSTRIDE);
    float4 q0 = wq[0], q1 = wq[1], q2 = wq[2], q3 = wq[3];
    float  e876 = reinterpret_cast<const float*>(wq)[16];

    SigMap M;
    M.Y0  = q0.x;  M.S2  = q0.y;  M.S5  = q0.z;  M.S9  = q0.w;
    M.W54 = q1.x;  M.W98 = q1.y;  M.W987= q1.z;  M.E1  = q1.w;
    M.E3  = q2.x;  M.E4  = q2.y;  M.E43 = q2.z;  M.E6  = q2.w;
    M.E7  = q3.x;  M.E76 = q3.y;  M.E8  = q3.z;  M.E87 = q3.w;
    M.E876= e876;

#pragma unroll
    for (int o = 1; o < 32; o <<= 1)
        M = sig_compose(M, sig_shfl_down(M, o));   // lane 0 exact after tree

    if (lane == 0) out[chain] = M.Y0;   // initial state zero -> Y = Y0
}

// ---------------- Launch ----------------
extern "C" void kernel_launch(void* const* d_in, const int* in_sizes, int n_in,
                              void* d_out, int out_size)
{
    const float* x    = (const float*)d_in[0];  // (32, 2048, 63) f32
    const float* kern = (const float*)d_in[1];  // (64, 10, 64)  f32

    cudaFuncSetAttribute(lrsig_fused, cudaFuncAttributeMaxDynamicSharedMemorySize,
                         SMEM_TOTAL);

    lrsig_fused<<<dim3(NCH, BB), 256, SMEM_TOTAL>>>(x, kern);
    lrsig_combine<<<NCHAIN / 8, 256>>>((float*)d_out);
}

// round 17
// speedup vs baseline: 1.2485x; 1.0354x over previous
#include <cuda_runtime.h>
#include <cuda_fp16.h>
#include <cstdint>
#include <cstddef>

// Problem constants
#define BB     32
#define TT     2048
#define FIN    63
#define FDIM   64
#define LUDIM  640
#define NCH    32      // chunks of 64 timesteps
#define TCH    64
#define NCHAIN 2048

// smem layout — total 104,448 B -> 2 CTAs/SM
#define XSTR   72      // Xh row stride (fp16 elems)
#define KSTR   72      // K stage stride (fp16 elems): 64 cols + 8 pad (144 B/row)
#define PSTR   260     // sP row stride (floats)
#define OFF_XH 0               // 64*72*2 = 9216
#define OFF_KH 9216
#define OFF_KL 18432
#define OFF_MAPS 27648         // 4*64*10*4 = 10240
#define OFF_SP 37888
#define SMEM_TOTAL (OFF_SP + TCH * PSTR * 4)   // 104448

#define WSTRIDE 20     // g_W record stride (floats), 80 B, 16B-aligned

// g_W layout: [chain][c][20]
__device__ float g_W[(size_t)NCHAIN * NCH * WSTRIDE];

// ---------------- PTX helpers ----------------
__device__ __forceinline__ uint32_t smem_u32(const void* p) {
    uint32_t a;
    asm("{ .reg .u64 t; cvta.to.shared.u64 t, %1; cvt.u32.u64 %0, t; }" : "=r"(a) : "l"(p));
    return a;
}
__device__ __forceinline__ void ldsm_x4(uint32_t& r0, uint32_t& r1, uint32_t& r2, uint32_t& r3,
                                        uint32_t addr) {
    asm volatile("ldmatrix.sync.aligned.m8n8.x4.shared.b16 {%0,%1,%2,%3}, [%4];"
                 : "=r"(r0), "=r"(r1), "=r"(r2), "=r"(r3) : "r"(addr));
}
__device__ __forceinline__ void ldsm_x2t(uint32_t& r0, uint32_t& r1, uint32_t addr) {
    asm volatile("ldmatrix.sync.aligned.m8n8.x2.trans.shared.b16 {%0,%1}, [%2];"
                 : "=r"(r0), "=r"(r1) : "r"(addr));
}
__device__ __forceinline__ void mma_f16(float* c, const uint32_t* a, uint32_t b0, uint32_t b1) {
    asm volatile(
        "mma.sync.aligned.m16n8k16.row.col.f32.f16.f16.f32 "
        "{%0,%1,%2,%3}, {%4,%5,%6,%7}, {%8,%9}, {%0,%1,%2,%3};"
        : "+f"(c[0]), "+f"(c[1]), "+f"(c[2]), "+f"(c[3])
        : "r"(a[0]), "r"(a[1]), "r"(a[2]), "r"(a[3]), "r"(b0), "r"(b1));
}
__device__ __forceinline__ uint32_t pack_h2(__half a, __half b) {
    __half2 h = __halves2half2(a, b);
    return *reinterpret_cast<uint32_t*>(&h);
}

// ---------------- Chen map (combine kernel) ----------------
struct SigMap {
    float Y0,S2,S5,S9,W54,W98,W987,E1,E3,E4,E43,E6,E7,E76,E8,E87,E876;
};

__device__ __forceinline__ SigMap sig_compose(const SigMap& A, const SigMap& B) {
    SigMap C;
    C.E1   = A.E1 + B.E1;
    C.E3   = A.E3 + B.E3;
    C.E6   = A.E6 + B.E6;
    C.E4   = A.E4 + B.E4;
    C.E43  = A.E43 + A.E3 * B.E4 + B.E43;
    C.E7   = A.E7 + B.E7;
    C.E76  = A.E76 + A.E6 * B.E7 + B.E76;
    C.E8   = A.E8 + B.E8;
    C.E87  = A.E87 + A.E7 * B.E8 + B.E87;
    C.E876 = A.E876 + A.E76 * B.E8 + A.E6 * B.E87 + B.E876;
    C.S2   = A.S2 + B.S2;
    C.S5   = A.S5 + B.S5;
    C.S9   = A.S9 + B.S9;
    C.W54  = A.W54 + A.E4 * B.S5 + B.W54;
    C.W98  = A.W98 + A.E8 * B.S9 + B.W98;
    C.W987 = A.W987 + A.E87 * B.S9 + A.E7 * B.W98 + B.W987;
    C.Y0   = A.Y0 + B.Y0 + A.E1 * B.S2 + A.E43 * B.S5 + A.E3 * B.W54
           + A.E876 * B.S9 + A.E76 * B.W98 + A.E6 * B.W987;
    return C;
}

// ---------------- Fused kernel: m = dX @ K (fp16 2-term) + 3-pass scan ----------------
// Grid (NCH, BB) = (32, 32), 256 threads, 2 CTAs/SM.
// Warp tile m64 x n8 (warp w owns cols w*8..w*8+7 of each 64-col stage):
// B fragments unique per warp -> ZERO ldsm redundancy (ldsm.x2.trans).
// A fragments: 4 mt-tiles x 4 ks x 4 regs = 64 regs, loaded once.
extern "C" __global__ void __launch_bounds__(256, 2)
lrsig_fused(const float* __restrict__ x, const float* __restrict__ kern)
{
    extern __shared__ char smem[];
    float* sP    = reinterpret_cast<float*>(smem + OFF_SP);
    float* sMaps = reinterpret_cast<float*>(smem + OFF_MAPS);
    const uint32_t sb = smem_u32(smem);

    const int tid  = threadIdx.x;
    const int lane = tid & 31;
    const int w    = tid >> 5;     // n8 group: cols w*8 .. w*8+7
    const int c    = blockIdx.x;
    const int b    = blockIdx.y;
    const int t0   = c * TCH;

    // K prefetch: stage = 64 f-rows x 16 fp32-uint4 = 1024 uint4, 4 per thread.
    const uint4* kernF4 = reinterpret_cast<const uint4*>(kern);   // 160 uint4/row
    const int v  = tid & 15;
    const int fb = tid >> 4;

    // Prefetch stage 0 (overlaps dX fill)
    uint4 kf[4];
#pragma unroll
    for (int r = 0; r < 4; r++)
        kf[r] = kernF4[(fb + 16 * r) * 160 + v];

    // ---- Xh tile (fp16), [t][f], stride 72; exact fp32 diff then 1 cvt ----
    for (int e = tid; e < TCH * FDIM; e += 256) {
        int tl = e >> 6, f = e & 63;
        int t = t0 + tl;
        float vv;
        if (t == 0)      vv = 0.0f;                                  // m[0] = 0
        else if (f < FIN) {
            const float* xr = x + ((size_t)b * TT + t) * FIN + f;
            vv = xr[0] - xr[-FIN];
        } else            vv = 2.0f / 2047.0f;                       // d(time)
        *reinterpret_cast<__half*>(smem + OFF_XH + (tl * XSTR + f) * 2) =
            __float2half_rn(vv);
    }
    __syncthreads();

    // ---- Preload A fragments once (m64: 4 mt-tiles x 4 ks = 64 regs) ----
    const uint32_t a_off = (uint32_t)((lane & 15) * XSTR + ((lane >> 4) << 3)) * 2;
    uint32_t Ah[4][4][4];
#pragma unroll
    for (int mt = 0; mt < 4; mt++)
#pragma unroll
        for (int ks = 0; ks < 4; ks++) {
            uint32_t ra = (uint32_t)(mt * 16 * XSTR + ks * 16) * 2 + a_off;
            ldsm_x4(Ah[mt][ks][0], Ah[mt][ks][1], Ah[mt][ks][2], Ah[mt][ks][3],
                    sb + OFF_XH + ra);
        }

    // x2t lane offset: lanes 0-7 -> k rows 0-7, lanes 8-15 -> k rows 8-15
    // (lanes 16-31 addresses unused; masked to valid range). Column = w*8.
    const uint32_t b_off = (uint32_t)(((((lane & 15) >> 3) << 3) + (lane & 7)) * KSTR
                                      + w * 8) * 2;

    // Commit stage 0: split fp32 -> (hi, lo) fp16
#pragma unroll
    for (int r = 0; r < 4; r++) {
        float4 f4 = *reinterpret_cast<float4*>(&kf[r]);
        __half hx = __float2half_rn(f4.x), hy = __float2half_rn(f4.y);
        __half hz = __float2half_rn(f4.z), hw = __float2half_rn(f4.w);
        __half lx = __float2half_rn(f4.x - __half2float(hx));
        __half ly = __float2half_rn(f4.y - __half2float(hy));
        __half lz = __float2half_rn(f4.z - __half2float(hz));
        __half lw = __float2half_rn(f4.w - __half2float(hw));
        int off = (fb + 16 * r) * 144 + v * 8;
        *reinterpret_cast<uint2*>(smem + OFF_KH + off) =
            make_uint2(pack_h2(hx, hy), pack_h2(hz, hw));
        *reinterpret_cast<uint2*>(smem + OFF_KL + off) =
            make_uint2(pack_h2(lx, ly), pack_h2(lz, lw));
    }
    __syncthreads();   // K stage 0 ready

    float Y0acc = 0.0f;

    // ---- Stage loop: 10 stages of 64 cols ----
    for (int j = 0; j < 10; j++) {
        // Prefetch K fp32 for stage j+1 (overlaps this stage's MMA)
        if (j < 9) {
#pragma unroll
            for (int r = 0; r < 4; r++)
                kf[r] = kernF4[(fb + 16 * r) * 160 + (j + 1) * 16 + v];
        }

        float C[4][4];
#pragma unroll
        for (int mt = 0; mt < 4; mt++)
#pragma unroll
            for (int i = 0; i < 4; i++) C[mt][i] = 0.0f;

#pragma unroll
        for (int ks = 0; ks < 4; ks++) {
            // One n8 x k16 B tile per warp per ks (hi + lo): 2 ldsm.x2t
            uint32_t rb = (uint32_t)(ks * 16 * KSTR) * 2 + b_off;
            uint32_t Bh0, Bh1, Bl0, Bl1;
            ldsm_x2t(Bh0, Bh1, sb + OFF_KH + rb);
            ldsm_x2t(Bl0, Bl1, sb + OFF_KL + rb);
#pragma unroll
            for (int mt = 0; mt < 4; mt++) {
                mma_f16(C[mt], Ah[mt][ks], Bh0, Bh1);
                mma_f16(C[mt], Ah[mt][ks], Bl0, Bl1);
            }
        }

        // Epilogue into sP at pass-local columns
        {
            const int ps = (j < 3) ? 0 : ((j < 6) ? 3 : 6);
            const int cb = (j - ps) * 64;
            const int col = cb + w * 8 + (lane & 3) * 2;
#pragma unroll
            for (int mt = 0; mt < 4; mt++) {
                int r = mt * 16 + (lane >> 2);
                float* q0 = sP + (size_t)r * PSTR + col;
                float* q1 = sP + (size_t)(r + 8) * PSTR + col;
                *reinterpret_cast<float2*>(q0) = make_float2(C[mt][0], C[mt][1]);
                *reinterpret_cast<float2*>(q1) = make_float2(C[mt][2], C[mt][3]);
            }
        }

        // ---- Pass-end scans ----
        if (j == 2 || j == 5 || j == 9) {
            __syncthreads();     // sP complete for this pass
            const int u  = tid & 63;
            const int qc = tid >> 6;        // 0..3, 16 rows each
            const int r0 = qc * 16;
            float* mp = sMaps + (size_t)(qc * 64 + u) * 10;

            if (j == 2) {
                float y0 = 0.f, e1 = 0.f, S2 = 0.f, W21 = 0.f;
#pragma unroll 4
                for (int i = 0; i < 16; i++) {
                    const float* p = sP + (size_t)(r0 + i) * PSTR + u;
                    float m0 = p[0], m1 = p[64], m2 = p[128];
                    y0 += m0;
                    W21 = fmaf(m2, e1, W21);  S2 += m2;  e1 += m1;
                }
                mp[0] = y0; mp[1] = e1; mp[2] = S2; mp[3] = W21;
                __syncthreads();
                if (tid < 64) {
                    float Y = 0.f, E1 = 0.f, S2t = 0.f, W21t = 0.f;
#pragma unroll
                    for (int q = 0; q < 4; q++) {
                        const float* s = sMaps + (size_t)(q * 64 + tid) * 10;
                        W21t += E1 * s[2] + s[3];
                        E1   += s[1];  S2t += s[2];  Y += s[0];
                    }
                    Y0acc = Y + W21t;
                    float* wp = g_W + ((size_t)(b * 64 + tid) * NCH + c) * WSTRIDE;
                    wp[7] = E1;  wp[1] = S2t;
                }
            } else if (j == 5) {
                float e3=0.f,e4=0.f,e43=0.f,S5=0.f,W54=0.f,W543=0.f;
#pragma unroll 4
                for (int i = 0; i < 16; i++) {
                    const float* p = sP + (size_t)(r0 + i) * PSTR + u;
                    float m3 = p[0], m4 = p[64], m5 = p[128];
                    W54  = fmaf(m5, e4,  W54);
                    W543 = fmaf(m5, e43, W543);  S5 += m5;
                    e43  = fmaf(m4, e3,  e43);
                    e3 += m3;  e4 += m4;
                }
                mp[0]=e3; mp[1]=e4; mp[2]=e43; mp[3]=S5; mp[4]=W54; mp[5]=W543;
                __syncthreads();
                if (tid < 64) {
                    float E3=0.f,E4=0.f,E43=0.f,S5t=0.f,W54t=0.f,W543t=0.f;
#pragma unroll
                    for (int q = 0; q < 4; q++) {
                        const float* s = sMaps + (size_t)(q * 64 + tid) * 10;
                        W543t += E43 * s[3] + E3 * s[4] + s[5];
                        W54t  += E4 * s[3] + s[4];
                        E43   += E3 * s[1] + s[2];
                        E3 += s[0];  E4 += s[1];  S5t += s[3];
                    }
                    Y0acc += W543t;
                    float* wp = g_W + ((size_t)(b * 64 + tid) * NCH + c) * WSTRIDE;
                    wp[8]=E3; wp[9]=E4; wp[10]=E43; wp[2]=S5t; wp[4]=W54t;
                }
            } else {
                float e6=0.f,e7=0.f,e8=0.f,e76=0.f,e87=0.f,e876=0.f;
                float S9=0.f,W98=0.f,W987=0.f,W9876=0.f;
#pragma unroll 4
                for (int i = 0; i < 16; i++) {
                    const float* p = sP + (size_t)(r0 + i) * PSTR + u;
                    float m6 = p[0], m7 = p[64], m8 = p[128], m9 = p[192];
                    W98   = fmaf(m9, e8,   W98);
                    W987  = fmaf(m9, e87,  W987);
                    W9876 = fmaf(m9, e876, W9876);  S9 += m9;
                    e876  = fmaf(m8, e76,  e876);
                    e87   = fmaf(m8, e7,   e87);
                    e76   = fmaf(m7, e6,   e76);
                    e6 += m6;  e7 += m7;  e8 += m8;
                }
                mp[0]=e6; mp[1]=e7; mp[2]=e8; mp[3]=e76; mp[4]=e87;
                mp[5]=e876; mp[6]=S9; mp[7]=W98; mp[8]=W987; mp[9]=W9876;
                __syncthreads();
                if (tid < 64) {
                    float E6=0.f,E7=0.f,E8=0.f,E76=0.f,E87=0.f,E876=0.f;
                    float S9t=0.f,W98t=0.f,W987t=0.f,W9876t=0.f;
#pragma unroll
                    for (int q = 0; q < 4; q++) {
                        const float* s = sMaps + (size_t)(q * 64 + tid) * 10;
                        W9876t += E876 * s[6] + E76 * s[7] + E6 * s[8] + s[9];
                        W987t  += E87 * s[6] + E7 * s[7] + s[8];
                        W98t   += E8 * s[6] + s[7];
                        E876   += E76 * s[2] + E6 * s[4] + s[5];
                        E87    += E7 * s[2] + s[4];
                        E76    += E6 * s[1] + s[3];
                        E6 += s[0];  E7 += s[1];  E8 += s[2];  S9t += s[6];
                    }
                    Y0acc += W9876t;
                    float* wp = g_W + ((size_t)(b * 64 + tid) * NCH + c) * WSTRIDE;
                    wp[11]=E6; wp[12]=E7; wp[13]=E76; wp[14]=E8; wp[15]=E87;
                    wp[16]=E876; wp[3]=S9t; wp[5]=W98t; wp[6]=W987t;
                    wp[0]=Y0acc;
                }
            }
        }

        // ---- Commit K stage j+1 ----
        if (j < 9) {
            __syncthreads();   // all ldsm reads of stage j complete
#pragma unroll
            for (int r = 0; r < 4; r++) {
                float4 f4 = *reinterpret_cast<float4*>(&kf[r]);
                __half hx = __float2half_rn(f4.x), hy = __float2half_rn(f4.y);
                __half hz = __float2half_rn(f4.z), hw = __float2half_rn(f4.w);
                __half lx = __float2half_rn(f4.x - __half2float(hx));
                __half ly = __float2half_rn(f4.y - __half2float(hy));
                __half lz = __float2half_rn(f4.z - __half2float(hz));
                __half lw = __float2half_rn(f4.w - __half2float(hw));
                int off = (fb + 16 * r) * 144 + v * 8;
                *reinterpret_cast<uint2*>(smem + OFF_KH + off) =
                    make_uint2(pack_h2(hx, hy), pack_h2(hz, hw));
                *reinterpret_cast<uint2*>(smem + OFF_KL + off) =
                    make_uint2(pack_h2(lx, ly), pack_h2(lz, lw));
            }
            __syncthreads();   // K stage j+1 ready
        }
    }
}

// ---------------- Combine: warp-tree composition over 32 chunks ----------------
__device__ __forceinline__ SigMap sig_shfl_down(const SigMap& m, int o) {
    SigMap r;
    r.Y0  = __shfl_down_sync(0xffffffffu, m.Y0,  o);
    r.S2  = __shfl_down_sync(0xffffffffu, m.S2,  o);
    r.S5  = __shfl_down_sync(0xffffffffu, m.S5,  o);
    r.S9  = __shfl_down_sync(0xffffffffu, m.S9,  o);
    r.W54 = __shfl_down_sync(0xffffffffu, m.W54, o);
    r.W98 = __shfl_down_sync(0xffffffffu, m.W98, o);
    r.W987= __shfl_down_sync(0xffffffffu, m.W987,o);
    r.E1  = __shfl_down_sync(0xffffffffu, m.E1,  o);
    r.E3  = __shfl_down_sync(0xffffffffu, m.E3,  o);
    r.E4  = __shfl_down_sync(0xffffffffu, m.E4,  o);
    r.E43 = __shfl_down_sync(0xffffffffu, m.E43, o);
    r.E6  = __shfl_down_sync(0xffffffffu, m.E6,  o);
    r.E7  = __shfl_down_sync(0xffffffffu, m.E7,  o);
    r.E76 = __shfl_down_sync(0xffffffffu, m.E76, o);
    r.E8  = __shfl_down_sync(0xffffffffu, m.E8,  o);
    r.E87 = __shfl_down_sync(0xffffffffu, m.E87, o);
    r.E876= __shfl_down_sync(0xffffffffu, m.E876,o);
    return r;
}

extern "C" __global__ void __launch_bounds__(256)
lrsig_combine(float* __restrict__ out)
{
    const int chain = blockIdx.x * 8 + (threadIdx.x >> 5);
    const int lane  = threadIdx.x & 31;

    const float4* wq = reinterpret_cast<const float4*>(
        g_W + ((size_t)chain * NCH + lane) * WSTRIDE);
    float4 q0 = wq[0], q1 = wq[1], q2 = wq[2], q3 = wq[3];
    float  e876 = reinterpret_cast<const float*>(wq)[16];

    SigMap M;
    M.Y0  = q0.x;  M.S2  = q0.y;  M.S5  = q0.z;  M.S9  = q0.w;
    M.W54 = q1.x;  M.W98 = q1.y;  M.W987= q1.z;  M.E1  = q1.w;
    M.E3  = q2.x;  M.E4  = q2.y;  M.E43 = q2.z;  M.E6  = q2.w;
    M.E7  = q3.x;  M.E76 = q3.y;  M.E8  = q3.z;  M.E87 = q3.w;
    M.E876= e876;

#pragma unroll
    for (int o = 1; o < 32; o <<= 1)
        M = sig_compose(M, sig_shfl_down(M, o));   // lane 0 exact after tree

    if (lane == 0) out[chain] = M.Y0;   // initial state zero -> Y = Y0
}

// ---------------- Launch ----------------
extern "C" void kernel_launch(void* const* d_in, const int* in_sizes, int n_in,
                              void* d_out, int out_size)
{
    const float* x    = (const float*)d_in[0];  // (32, 2048, 63) f32
    const float* kern = (const float*)d_in[1];  // (64, 10, 64)  f32

    cudaFuncSetAttribute(lrsig_fused, cudaFuncAttributeMaxDynamicSharedMemorySize,
                         SMEM_TOTAL);

    lrsig_fused<<<dim3(NCH, BB), 256, SMEM_TOTAL>>>(x, kern);
    lrsig_combine<<<NCHAIN / 8, 256>>>((float*)d_out);
}